// round 2
// baseline (speedup 1.0000x reference)
#include <cuda_runtime.h>
#include <cuda_bf16.h>
#include <math.h>

// ---------------------------------------------------------------------------
// LLaDA router: logits = x @ W^T  (N=B*S tokens, D feat, E=8 experts)
//   -> LayerNorm(E) -> /(|T|+1e-6) -> softmax -> top-2 dispatch
//   -> router_loss = 0.01*mean(rl^2) + 0.01*KL(ideal||actual)/E
// Out layout: [routing_weights N*E][dispatch N*E][loss 1]
// ---------------------------------------------------------------------------

#define EXPERTS 8
#define TOK_PER_WARP 4
#define WARPS_PER_BLOCK 8
#define TOK_PER_BLOCK (TOK_PER_WARP * WARPS_PER_BLOCK)   // 32
#define MAX_BLOCKS 8192

// per-block partials: [block][0..7]=sum routing_weights per expert, [8]=sum rl^2
__device__ float g_part[MAX_BLOCKS * 9];

// ---- packed f32x2 helpers --------------------------------------------------
typedef unsigned long long u64;

__device__ __forceinline__ u64 pk2(float lo, float hi) {
    u64 r;
    asm("mov.b64 %0, {%1, %2};" : "=l"(r) : "f"(lo), "f"(hi));
    return r;
}
__device__ __forceinline__ u64 fma2(u64 a, u64 b, u64 c) {
    u64 d;
    asm("fma.rn.f32x2 %0, %1, %2, %3;" : "=l"(d) : "l"(a), "l"(b), "l"(c));
    return d;
}
__device__ __forceinline__ u64 add2(u64 a, u64 b) {
    u64 d;
    asm("add.rn.f32x2 %0, %1, %2;" : "=l"(d) : "l"(a), "l"(b));
    return d;
}
__device__ __forceinline__ void unpk2(u64 v, float& lo, float& hi) {
    asm("mov.b64 {%0, %1}, %2;" : "=f"(lo), "=f"(hi) : "l"(v));
}
__device__ __forceinline__ float f4c(const float4& v, int d) {
    return (d == 0) ? v.x : (d == 1) ? v.y : (d == 2) ? v.z : v.w;
}

__global__ __launch_bounds__(256, 2)
void router_main(const float* __restrict__ x,
                 const float* __restrict__ W,
                 const float* __restrict__ gamma,
                 const float* __restrict__ beta,
                 const float* __restrict__ temp,
                 float* __restrict__ out,
                 int N, int D)
{
    __shared__ float s_logits[TOK_PER_BLOCK * EXPERTS];

    const int lane = threadIdx.x & 31;
    const int warp = threadIdx.x >> 5;
    const int tok0 = blockIdx.x * TOK_PER_BLOCK + warp * TOK_PER_WARP;

    // clamp token indices (duplicate work for tail tokens; discarded later)
    int t0 = min(tok0 + 0, N - 1);
    int t1 = min(tok0 + 1, N - 1);
    int t2 = min(tok0 + 2, N - 1);
    int t3 = min(tok0 + 3, N - 1);
    const float* xp0 = x + (size_t)t0 * D;
    const float* xp1 = x + (size_t)t1 * D;
    const float* xp2 = x + (size_t)t2 * D;
    const float* xp3 = x + (size_t)t3 * D;

    // acc[token][expert-pair], packed {e=2j, e=2j+1}
    u64 acc[TOK_PER_WARP][EXPERTS / 2];
#pragma unroll
    for (int t = 0; t < TOK_PER_WARP; ++t)
#pragma unroll
        for (int j = 0; j < EXPERTS / 2; ++j) acc[t][j] = 0ull;

    const int nIter = D >> 7;   // D / 128 (warp covers 128 floats per sweep)
    for (int i = 0; i < nIter; ++i) {
        const int d0 = (i << 7) + (lane << 2);

        float4 xa = __ldg((const float4*)(xp0 + d0));
        float4 xb = __ldg((const float4*)(xp1 + d0));
        float4 xc = __ldg((const float4*)(xp2 + d0));
        float4 xd = __ldg((const float4*)(xp3 + d0));

        float4 wv[EXPERTS];
#pragma unroll
        for (int e = 0; e < EXPERTS; ++e)
            wv[e] = __ldg((const float4*)(W + (size_t)e * D + d0));

#pragma unroll
        for (int d = 0; d < 4; ++d) {
            u64 wp0 = pk2(f4c(wv[0], d), f4c(wv[1], d));
            u64 wp1 = pk2(f4c(wv[2], d), f4c(wv[3], d));
            u64 wp2 = pk2(f4c(wv[4], d), f4c(wv[5], d));
            u64 wp3 = pk2(f4c(wv[6], d), f4c(wv[7], d));

            u64 xx0 = pk2(f4c(xa, d), f4c(xa, d));
            u64 xx1 = pk2(f4c(xb, d), f4c(xb, d));
            u64 xx2 = pk2(f4c(xc, d), f4c(xc, d));
            u64 xx3 = pk2(f4c(xd, d), f4c(xd, d));

            acc[0][0] = fma2(xx0, wp0, acc[0][0]);
            acc[0][1] = fma2(xx0, wp1, acc[0][1]);
            acc[0][2] = fma2(xx0, wp2, acc[0][2]);
            acc[0][3] = fma2(xx0, wp3, acc[0][3]);
            acc[1][0] = fma2(xx1, wp0, acc[1][0]);
            acc[1][1] = fma2(xx1, wp1, acc[1][1]);
            acc[1][2] = fma2(xx1, wp2, acc[1][2]);
            acc[1][3] = fma2(xx1, wp3, acc[1][3]);
            acc[2][0] = fma2(xx2, wp0, acc[2][0]);
            acc[2][1] = fma2(xx2, wp1, acc[2][1]);
            acc[2][2] = fma2(xx2, wp2, acc[2][2]);
            acc[2][3] = fma2(xx2, wp3, acc[2][3]);
            acc[3][0] = fma2(xx3, wp0, acc[3][0]);
            acc[3][1] = fma2(xx3, wp1, acc[3][1]);
            acc[3][2] = fma2(xx3, wp2, acc[3][2]);
            acc[3][3] = fma2(xx3, wp3, acc[3][3]);
        }
    }

    // butterfly reduce the 16 packed accumulators across the warp
#pragma unroll
    for (int m = 16; m >= 1; m >>= 1) {
#pragma unroll
        for (int t = 0; t < TOK_PER_WARP; ++t)
#pragma unroll
            for (int j = 0; j < EXPERTS / 2; ++j)
                acc[t][j] = add2(acc[t][j],
                                 __shfl_xor_sync(0xFFFFFFFFu, acc[t][j], m));
    }

    if (lane == 0) {
#pragma unroll
        for (int t = 0; t < TOK_PER_WARP; ++t)
#pragma unroll
            for (int j = 0; j < EXPERTS / 2; ++j) {
                float lo, hi;
                unpk2(acc[t][j], lo, hi);
                int lt = warp * TOK_PER_WARP + t;
                s_logits[lt * EXPERTS + 2 * j + 0] = lo;
                s_logits[lt * EXPERTS + 2 * j + 1] = hi;
            }
    }
    __syncthreads();

    // ---- epilogue: warp 0 handles the block's 32 tokens -------------------
    if (threadIdx.x < TOK_PER_BLOCK) {
        const int lt = threadIdx.x;
        const int g = blockIdx.x * TOK_PER_BLOCK + lt;
        const bool valid = (g < N);

        const float tinv = 1.0f / (fabsf(temp[0]) + 1e-6f);
        float gm[EXPERTS], bt[EXPERTS];
#pragma unroll
        for (int e = 0; e < EXPERTS; ++e) { gm[e] = gamma[e]; bt[e] = beta[e]; }

        float l[EXPERTS];
        float mu = 0.0f;
#pragma unroll
        for (int e = 0; e < EXPERTS; ++e) {
            l[e] = s_logits[lt * EXPERTS + e];
            mu += l[e];
        }
        mu *= (1.0f / EXPERTS);
        float var = 0.0f;
#pragma unroll
        for (int e = 0; e < EXPERTS; ++e) {
            float dlt = l[e] - mu;
            var += dlt * dlt;
        }
        var *= (1.0f / EXPERTS);
        const float rinv = rsqrtf(var + 1e-5f);

        float rl[EXPERTS];
        float zsum = 0.0f;
        float mx = -1e30f;
#pragma unroll
        for (int e = 0; e < EXPERTS; ++e) {
            float v = ((l[e] - mu) * rinv * gm[e] + bt[e]) * tinv;
            rl[e] = v;
            zsum += v * v;
            mx = fmaxf(mx, v);
        }
        float rw[EXPERTS];
        float ssum = 0.0f;
#pragma unroll
        for (int e = 0; e < EXPERTS; ++e) {
            rw[e] = expf(rl[e] - mx);
            ssum += rw[e];
        }
        const float sinv = 1.0f / ssum;
#pragma unroll
        for (int e = 0; e < EXPERTS; ++e) rw[e] *= sinv;

        // top-2 (lowest index wins ties, matching lax.top_k)
        int i1 = 0; float w1 = rw[0];
#pragma unroll
        for (int e = 1; e < EXPERTS; ++e)
            if (rw[e] > w1) { w1 = rw[e]; i1 = e; }
        int i2 = -1; float w2 = -1.0f;
#pragma unroll
        for (int e = 0; e < EXPERTS; ++e)
            if (e != i1 && rw[e] > w2) { w2 = rw[e]; i2 = e; }
        const float nrm = 1.0f / (w1 + w2 + 1e-6f);
        const float d1 = w1 * nrm, d2 = w2 * nrm;

        if (valid) {
            const size_t NE = (size_t)N * EXPERTS;
            float4* rwo = (float4*)(out + (size_t)g * EXPERTS);
            rwo[0] = make_float4(rw[0], rw[1], rw[2], rw[3]);
            rwo[1] = make_float4(rw[4], rw[5], rw[6], rw[7]);
            float disp[EXPERTS];
#pragma unroll
            for (int e = 0; e < EXPERTS; ++e)
                disp[e] = (e == i1) ? d1 : (e == i2) ? d2 : 0.0f;
            float4* dpo = (float4*)(out + NE + (size_t)g * EXPERTS);
            dpo[0] = make_float4(disp[0], disp[1], disp[2], disp[3]);
            dpo[1] = make_float4(disp[4], disp[5], disp[6], disp[7]);
        }

        // block partials (deterministic: warp reduce then single store)
        float zc = valid ? zsum : 0.0f;
        float ec[EXPERTS];
#pragma unroll
        for (int e = 0; e < EXPERTS; ++e) ec[e] = valid ? rw[e] : 0.0f;

#pragma unroll
        for (int m = 16; m >= 1; m >>= 1) {
            zc += __shfl_xor_sync(0xFFFFFFFFu, zc, m);
#pragma unroll
            for (int e = 0; e < EXPERTS; ++e)
                ec[e] += __shfl_xor_sync(0xFFFFFFFFu, ec[e], m);
        }
        if (lane == 0) {
            float* p = &g_part[(size_t)blockIdx.x * 9];
#pragma unroll
            for (int e = 0; e < EXPERTS; ++e) p[e] = ec[e];
            p[8] = zc;
        }
    }
}

// Deterministic final reduction: 9 warps, one per partial column.
__global__ void router_loss_k(float* __restrict__ out, int nb, int N, size_t off)
{
    __shared__ float s[9];
    const int w = threadIdx.x >> 5;
    const int lane = threadIdx.x & 31;
    if (w < 9) {
        float v = 0.0f;
        for (int k = lane; k < nb; k += 32) v += g_part[(size_t)k * 9 + w];
#pragma unroll
        for (int m = 16; m >= 1; m >>= 1)
            v += __shfl_xor_sync(0xFFFFFFFFu, v, m);
        if (lane == 0) s[w] = v;
    }
    __syncthreads();
    if (threadIdx.x == 0) {
        const float invN = 1.0f / (float)N;
        float z = s[8] * invN * (1.0f / EXPERTS);
        float lb = 0.0f;
        const float ideal = 1.0f / EXPERTS;
#pragma unroll
        for (int e = 0; e < EXPERTS; ++e) {
            float actual = s[e] * invN;
            lb += ideal * (logf(ideal) - logf(actual));
        }
        lb *= (1.0f / EXPERTS);
        out[off] = 0.01f * z + 0.01f * lb;
    }
}

extern "C" void kernel_launch(void* const* d_in, const int* in_sizes, int n_in,
                              void* d_out, int out_size)
{
    const float* x     = (const float*)d_in[0];
    const float* W     = (const float*)d_in[1];
    const float* gamma = (const float*)d_in[2];
    const float* beta  = (const float*)d_in[3];
    const float* temp  = (const float*)d_in[4];
    float* out = (float*)d_out;

    const int E = in_sizes[2];           // 8
    const int D = in_sizes[1] / E;       // 2048
    const int N = in_sizes[0] / D;       // 16384

    const int nb = (N + TOK_PER_BLOCK - 1) / TOK_PER_BLOCK;

    router_main<<<nb, 256>>>(x, W, gamma, beta, temp, out, N, D);
    router_loss_k<<<1, 288>>>(out, nb, N, (size_t)2 * N * EXPERTS);
}

// round 3
// speedup vs baseline: 1.1044x; 1.1044x over previous
#include <cuda_runtime.h>
#include <cuda_bf16.h>
#include <math.h>

// ---------------------------------------------------------------------------
// LLaDA router: logits = x @ W^T  (N=B*S tokens, D feat, E=8 experts)
//   -> LayerNorm(E) -> /(|T|+1e-6) -> softmax -> top-2 dispatch
//   -> router_loss = 0.01*mean(rl^2) + 0.01*KL(ideal||actual)/E
// Out layout: [routing_weights N*E][dispatch N*E][loss 1]
// Single fused kernel; last block (atomic ticket) reduces the loss.
// ---------------------------------------------------------------------------

#define EXPERTS 8
#define TOK_PER_WARP 4
#define WARPS_PER_BLOCK 8
#define TOK_PER_BLOCK (TOK_PER_WARP * WARPS_PER_BLOCK)   // 32
#define MAX_BLOCKS 8192

// per-block partials: [block][0..7]=sum routing_weights per expert, [8]=sum rl^2
__device__ float g_part[MAX_BLOCKS * 9];
__device__ unsigned int g_ctr = 0;   // last-block ticket; reset by last block

// ---- packed f32x2 helpers --------------------------------------------------
typedef unsigned long long u64;

__device__ __forceinline__ u64 pk2(float lo, float hi) {
    u64 r;
    asm("mov.b64 %0, {%1, %2};" : "=l"(r) : "f"(lo), "f"(hi));
    return r;
}
__device__ __forceinline__ u64 fma2(u64 a, u64 b, u64 c) {
    u64 d;
    asm("fma.rn.f32x2 %0, %1, %2, %3;" : "=l"(d) : "l"(a), "l"(b), "l"(c));
    return d;
}
__device__ __forceinline__ u64 add2(u64 a, u64 b) {
    u64 d;
    asm("add.rn.f32x2 %0, %1, %2;" : "=l"(d) : "l"(a), "l"(b));
    return d;
}
__device__ __forceinline__ void unpk2(u64 v, float& lo, float& hi) {
    asm("mov.b64 {%0, %1}, %2;" : "=f"(lo), "=f"(hi) : "l"(v));
}
__device__ __forceinline__ float f4c(const float4& v, int d) {
    return (d == 0) ? v.x : (d == 1) ? v.y : (d == 2) ? v.z : v.w;
}

__global__ __launch_bounds__(256, 2)
void router_main(const float* __restrict__ x,
                 const float* __restrict__ W,
                 const float* __restrict__ gamma,
                 const float* __restrict__ beta,
                 const float* __restrict__ temp,
                 float* __restrict__ out,
                 int N, int D)
{
    __shared__ float s_logits[TOK_PER_BLOCK * EXPERTS];
    __shared__ bool s_last;

    const int lane = threadIdx.x & 31;
    const int warp = threadIdx.x >> 5;
    const int tok0 = blockIdx.x * TOK_PER_BLOCK + warp * TOK_PER_WARP;

    // clamp token indices (duplicate work for tail tokens; discarded later)
    int t0 = min(tok0 + 0, N - 1);
    int t1 = min(tok0 + 1, N - 1);
    int t2 = min(tok0 + 2, N - 1);
    int t3 = min(tok0 + 3, N - 1);
    const float* xp0 = x + (size_t)t0 * D;
    const float* xp1 = x + (size_t)t1 * D;
    const float* xp2 = x + (size_t)t2 * D;
    const float* xp3 = x + (size_t)t3 * D;

    // acc[token][expert-pair], packed {e=2j, e=2j+1}
    u64 acc[TOK_PER_WARP][EXPERTS / 2];
#pragma unroll
    for (int t = 0; t < TOK_PER_WARP; ++t)
#pragma unroll
        for (int j = 0; j < EXPERTS / 2; ++j) acc[t][j] = 0ull;

    const int nIter = D >> 7;   // D / 128 (warp covers 128 floats per sweep)
    const int doff = lane << 2;

    // -------- software-pipelined mainloop: x double-buffered in registers ---
    float4 xa = __ldg((const float4*)(xp0 + doff));
    float4 xb = __ldg((const float4*)(xp1 + doff));
    float4 xc = __ldg((const float4*)(xp2 + doff));
    float4 xd = __ldg((const float4*)(xp3 + doff));

    for (int i = 0; i < nIter; ++i) {
        const int d0 = (i << 7) + doff;
        // next-iteration x prefetch (wrap to current on last iter; L1 hit)
        const int dn = ((i + 1 < nIter) ? ((i + 1) << 7) : (i << 7)) + doff;
        float4 na = __ldg((const float4*)(xp0 + dn));
        float4 nb_ = __ldg((const float4*)(xp1 + dn));
        float4 nc = __ldg((const float4*)(xp2 + dn));
        float4 nd = __ldg((const float4*)(xp3 + dn));

        float4 wv[EXPERTS];
#pragma unroll
        for (int e = 0; e < EXPERTS; ++e)
            wv[e] = __ldg((const float4*)(W + (size_t)e * D + d0));

#pragma unroll
        for (int d = 0; d < 4; ++d) {
            u64 wp0 = pk2(f4c(wv[0], d), f4c(wv[1], d));
            u64 wp1 = pk2(f4c(wv[2], d), f4c(wv[3], d));
            u64 wp2 = pk2(f4c(wv[4], d), f4c(wv[5], d));
            u64 wp3 = pk2(f4c(wv[6], d), f4c(wv[7], d));

            u64 xx0 = pk2(f4c(xa, d), f4c(xa, d));
            u64 xx1 = pk2(f4c(xb, d), f4c(xb, d));
            u64 xx2 = pk2(f4c(xc, d), f4c(xc, d));
            u64 xx3 = pk2(f4c(xd, d), f4c(xd, d));

            acc[0][0] = fma2(xx0, wp0, acc[0][0]);
            acc[0][1] = fma2(xx0, wp1, acc[0][1]);
            acc[0][2] = fma2(xx0, wp2, acc[0][2]);
            acc[0][3] = fma2(xx0, wp3, acc[0][3]);
            acc[1][0] = fma2(xx1, wp0, acc[1][0]);
            acc[1][1] = fma2(xx1, wp1, acc[1][1]);
            acc[1][2] = fma2(xx1, wp2, acc[1][2]);
            acc[1][3] = fma2(xx1, wp3, acc[1][3]);
            acc[2][0] = fma2(xx2, wp0, acc[2][0]);
            acc[2][1] = fma2(xx2, wp1, acc[2][1]);
            acc[2][2] = fma2(xx2, wp2, acc[2][2]);
            acc[2][3] = fma2(xx2, wp3, acc[2][3]);
            acc[3][0] = fma2(xx3, wp0, acc[3][0]);
            acc[3][1] = fma2(xx3, wp1, acc[3][1]);
            acc[3][2] = fma2(xx3, wp2, acc[3][2]);
            acc[3][3] = fma2(xx3, wp3, acc[3][3]);
        }
        xa = na; xb = nb_; xc = nc; xd = nd;
    }

    // butterfly reduce the 16 packed accumulators across the warp
#pragma unroll
    for (int m = 16; m >= 1; m >>= 1) {
#pragma unroll
        for (int t = 0; t < TOK_PER_WARP; ++t)
#pragma unroll
            for (int j = 0; j < EXPERTS / 2; ++j)
                acc[t][j] = add2(acc[t][j],
                                 __shfl_xor_sync(0xFFFFFFFFu, acc[t][j], m));
    }

    if (lane == 0) {
#pragma unroll
        for (int t = 0; t < TOK_PER_WARP; ++t)
#pragma unroll
            for (int j = 0; j < EXPERTS / 2; ++j) {
                float lo, hi;
                unpk2(acc[t][j], lo, hi);
                int lt = warp * TOK_PER_WARP + t;
                s_logits[lt * EXPERTS + 2 * j + 0] = lo;
                s_logits[lt * EXPERTS + 2 * j + 1] = hi;
            }
    }
    __syncthreads();

    // ---- epilogue: warp 0 handles the block's 32 tokens -------------------
    if (threadIdx.x < TOK_PER_BLOCK) {
        const int lt = threadIdx.x;
        const int g = blockIdx.x * TOK_PER_BLOCK + lt;
        const bool valid = (g < N);

        const float tinv = 1.0f / (fabsf(temp[0]) + 1e-6f);
        float gm[EXPERTS], bt[EXPERTS];
#pragma unroll
        for (int e = 0; e < EXPERTS; ++e) { gm[e] = gamma[e]; bt[e] = beta[e]; }

        float l[EXPERTS];
        float mu = 0.0f;
#pragma unroll
        for (int e = 0; e < EXPERTS; ++e) {
            l[e] = s_logits[lt * EXPERTS + e];
            mu += l[e];
        }
        mu *= (1.0f / EXPERTS);
        float var = 0.0f;
#pragma unroll
        for (int e = 0; e < EXPERTS; ++e) {
            float dlt = l[e] - mu;
            var += dlt * dlt;
        }
        var *= (1.0f / EXPERTS);
        const float rinv = rsqrtf(var + 1e-5f);

        float rl[EXPERTS];
        float zsum = 0.0f;
        float mx = -1e30f;
#pragma unroll
        for (int e = 0; e < EXPERTS; ++e) {
            float v = ((l[e] - mu) * rinv * gm[e] + bt[e]) * tinv;
            rl[e] = v;
            zsum += v * v;
            mx = fmaxf(mx, v);
        }
        float rw[EXPERTS];
        float ssum = 0.0f;
#pragma unroll
        for (int e = 0; e < EXPERTS; ++e) {
            rw[e] = expf(rl[e] - mx);
            ssum += rw[e];
        }
        const float sinv = 1.0f / ssum;
#pragma unroll
        for (int e = 0; e < EXPERTS; ++e) rw[e] *= sinv;

        // top-2 (lowest index wins ties, matching lax.top_k)
        int i1 = 0; float w1 = rw[0];
#pragma unroll
        for (int e = 1; e < EXPERTS; ++e)
            if (rw[e] > w1) { w1 = rw[e]; i1 = e; }
        int i2 = -1; float w2 = -1.0f;
#pragma unroll
        for (int e = 0; e < EXPERTS; ++e)
            if (e != i1 && rw[e] > w2) { w2 = rw[e]; i2 = e; }
        const float nrm = 1.0f / (w1 + w2 + 1e-6f);
        const float d1 = w1 * nrm, d2 = w2 * nrm;

        if (valid) {
            const size_t NE = (size_t)N * EXPERTS;
            float4* rwo = (float4*)(out + (size_t)g * EXPERTS);
            rwo[0] = make_float4(rw[0], rw[1], rw[2], rw[3]);
            rwo[1] = make_float4(rw[4], rw[5], rw[6], rw[7]);
            float disp[EXPERTS];
#pragma unroll
            for (int e = 0; e < EXPERTS; ++e)
                disp[e] = (e == i1) ? d1 : (e == i2) ? d2 : 0.0f;
            float4* dpo = (float4*)(out + NE + (size_t)g * EXPERTS);
            dpo[0] = make_float4(disp[0], disp[1], disp[2], disp[3]);
            dpo[1] = make_float4(disp[4], disp[5], disp[6], disp[7]);
        }

        // block partials (deterministic: warp reduce then single store)
        float zc = valid ? zsum : 0.0f;
        float ec[EXPERTS];
#pragma unroll
        for (int e = 0; e < EXPERTS; ++e) ec[e] = valid ? rw[e] : 0.0f;

#pragma unroll
        for (int m = 16; m >= 1; m >>= 1) {
            zc += __shfl_xor_sync(0xFFFFFFFFu, zc, m);
#pragma unroll
            for (int e = 0; e < EXPERTS; ++e)
                ec[e] += __shfl_xor_sync(0xFFFFFFFFu, ec[e], m);
        }
        if (lane == 0) {
            float* p = &g_part[(size_t)blockIdx.x * 9];
#pragma unroll
            for (int e = 0; e < EXPERTS; ++e) p[e] = ec[e];
            p[8] = zc;
        }
    }

    // ---- fused loss: last block reduces all partials ----------------------
    __syncthreads();
    if (threadIdx.x == 0) {
        __threadfence();
        unsigned int t = atomicAdd(&g_ctr, 1u);
        s_last = (t == gridDim.x - 1);
    }
    __syncthreads();

    if (s_last) {
        __shared__ float s_red[9];
        const int nb = gridDim.x;
        // 8 warps; warp w covers columns w, w+8, ... (9 columns total)
        for (int c = warp; c < 9; c += WARPS_PER_BLOCK) {
            float v = 0.0f;
            for (int k = lane; k < nb; k += 32) v += g_part[(size_t)k * 9 + c];
#pragma unroll
            for (int m = 16; m >= 1; m >>= 1)
                v += __shfl_xor_sync(0xFFFFFFFFu, v, m);
            if (lane == 0) s_red[c] = v;
        }
        __syncthreads();
        if (threadIdx.x == 0) {
            const float invN = 1.0f / (float)N;
            float z = s_red[8] * invN * (1.0f / EXPERTS);
            float lb = 0.0f;
            const float ideal = 1.0f / EXPERTS;
#pragma unroll
            for (int e = 0; e < EXPERTS; ++e) {
                float actual = s_red[e] * invN;
                lb += ideal * (logf(ideal) - logf(actual));
            }
            lb *= (1.0f / EXPERTS);
            out[(size_t)2 * N * EXPERTS] = 0.01f * z + 0.01f * lb;
            g_ctr = 0;   // reset for next graph replay (deterministic)
        }
    }
}

extern "C" void kernel_launch(void* const* d_in, const int* in_sizes, int n_in,
                              void* d_out, int out_size)
{
    const float* x     = (const float*)d_in[0];
    const float* W     = (const float*)d_in[1];
    const float* gamma = (const float*)d_in[2];
    const float* beta  = (const float*)d_in[3];
    const float* temp  = (const float*)d_in[4];
    float* out = (float*)d_out;

    const int E = in_sizes[2];           // 8
    const int D = in_sizes[1] / E;       // 2048
    const int N = in_sizes[0] / D;       // 16384

    const int nb = (N + TOK_PER_BLOCK - 1) / TOK_PER_BLOCK;

    router_main<<<nb, 256>>>(x, W, gamma, beta, temp, out, N, D);
}